// round 11
// baseline (speedup 1.0000x reference)
#include <cuda_runtime.h>
#include <cuda_fp16.h>
#include <cuda_bf16.h>
#include <math_constants.h>
#include <cstdint>

#define ENC_DIM 256
#define INT_DIM 256
#define MT 64                   // rows per CTA (M)
#define NT 256                  // hidden per CTA (N)
#define KC 32                   // k per staged chunk
#define NCHUNK (ENC_DIM / KC)   // 8
#define NKS (KC / 16)           // 2 k16 steps per chunk
#define P 20                    // smem pitch in u32 words (16 used + 4 pad)
#define ASZ (MT * P)            // 1280 words
#define BSZ (NT * P)            // 5120 words
#define STAGES 4
#define DYN_BYTES (STAGES * (ASZ + BSZ) * 4)   // 102400 -> 2 CTAs/SM
#define NTHR 256
#define NC 32                   // context chunks per batch

// Scratch (allocation-free rule: __device__ globals)
__device__ float  g_dp[64 * INT_DIM];          // dec_proj [B, I]
__device__ float  g_scores[64 * 2048];         // scores   [B, T]
__device__ __half g_w1h[INT_DIM * ENC_DIM];    // w1 as fp16, [n][k]
__device__ float  g_part[NC * 64 * ENC_DIM];   // context partials

// ---------------------------------------------------------------------------
// helpers
// ---------------------------------------------------------------------------
__device__ __forceinline__ float tanha(float x) {
    float y;
    asm("tanh.approx.f32 %0, %1;" : "=f"(y) : "f"(x));
    return y;
}
__device__ __forceinline__ void cp16(unsigned dst_s, const void* src) {
    asm volatile("cp.async.cg.shared.global [%0], [%1], 16;"
                 :: "r"(dst_s), "l"(src) : "memory");
}
__device__ __forceinline__ void cp_commit() {
    asm volatile("cp.async.commit_group;" ::: "memory");
}
template <int N>
__device__ __forceinline__ void cp_wait() {
    asm volatile("cp.async.wait_group %0;" :: "n"(N) : "memory");
}
__device__ __forceinline__ unsigned s2u(const void* p) {
    return (unsigned)__cvta_generic_to_shared(p);
}
__device__ __forceinline__ void ldsm4(unsigned r[4], unsigned addr) {
    asm volatile("ldmatrix.sync.aligned.m8n8.x4.shared.b16 "
                 "{%0,%1,%2,%3}, [%4];"
                 : "=r"(r[0]), "=r"(r[1]), "=r"(r[2]), "=r"(r[3])
                 : "r"(addr));
}
__device__ __forceinline__ void mma_f16(float d[4], const unsigned a[4],
                                        unsigned b0, unsigned b1) {
    asm volatile(
        "mma.sync.aligned.m16n8k16.row.col.f32.f16.f16.f32 "
        "{%0,%1,%2,%3}, {%4,%5,%6,%7}, {%8,%9}, {%0,%1,%2,%3};"
        : "+f"(d[0]), "+f"(d[1]), "+f"(d[2]), "+f"(d[3])
        : "r"(a[0]), "r"(a[1]), "r"(a[2]), "r"(a[3]), "r"(b0), "r"(b1));
}

// ---------------------------------------------------------------------------
// K0: fused prep. grid = 64 blocks x 256 threads.
//  - block b: dec_proj[b, :] via warp-per-32-outputs coalesced reduction
//  - block b also converts w1 elements [b*1024, b*1024+1024) to fp16
// ---------------------------------------------------------------------------
__global__ void prep_kernel(const float* __restrict__ dec,
                            const float* __restrict__ w2,
                            const float* __restrict__ w1,
                            __half* __restrict__ w1h,
                            float* __restrict__ dp) {
    __shared__ float ds[ENC_DIM];
    const int b = blockIdx.x;
    const int tid = threadIdx.x;
    const int lane = tid & 31, wid = tid >> 5;

    ds[tid] = dec[b * ENC_DIM + tid];

    // w1 -> fp16 slice (1024 elements per block, float4-wide)
    {
        const int base = b * 1024 + tid * 4;
        float4 wv = *reinterpret_cast<const float4*>(w1 + base);
        __half2 p0 = __floats2half2_rn(wv.x, wv.y);
        __half2 p1 = __floats2half2_rn(wv.z, wv.w);
        uint2 pk = make_uint2(*reinterpret_cast<uint32_t*>(&p0),
                              *reinterpret_cast<uint32_t*>(&p1));
        *reinterpret_cast<uint2*>(w1h + base) = pk;
    }
    __syncthreads();

    // dec_proj: warp wid handles outputs i in [wid*32, wid*32+32)
#pragma unroll 4
    for (int ii = 0; ii < 32; ++ii) {
        const int i = wid * 32 + ii;
        float acc = 0.f;
#pragma unroll
        for (int kk = 0; kk < 8; ++kk) {
            const int k = kk * 32 + lane;
            acc = fmaf(__ldg(w2 + i * ENC_DIM + k), ds[k], acc);
        }
#pragma unroll
        for (int o = 16; o; o >>= 1) acc += __shfl_xor_sync(0xffffffffu, acc, o);
        if (lane == 0) dp[b * INT_DIM + i] = acc;
    }
}

// ---------------------------------------------------------------------------
// K1: scores via fp16 mma m16n8k16 + ldmatrix, 4-stage cp.async pipeline,
// ONE __syncthreads per chunk. CTA = 64 rows x 256 n, 256 thr, 2 CTAs/SM.
// Warp w: m-half (w&1)*32 (h=2, B reused), n-quarter (w>>1)*64 (j=8).
// ---------------------------------------------------------------------------
__global__ void __launch_bounds__(NTHR, 2)
scores_mma_kernel(const float* __restrict__ enc,
                  const __half* __restrict__ w1h,
                  const float* __restrict__ dp,
                  const float* __restrict__ v,
                  float* __restrict__ scores,
                  int T) {
    extern __shared__ unsigned sm[];          // A0..A3 | B0..B3
    __shared__ float dps[INT_DIM], vs[INT_DIM], ssc[MT];

    const int tid  = threadIdx.x;
    const int wid  = tid >> 5;
    const int lane = tid & 31;
    const int t    = lane & 3;
    const int m0   = (wid & 1) * 32;
    const int nb   = (wid >> 1) * 64;
    const long long row0 = (long long)blockIdx.x * MT;
    const int b = (int)(row0 / T);

    dps[tid] = dp[b * INT_DIM + tid];
    vs[tid]  = __ldg(v + tid);
    if (tid < MT) ssc[tid] = 0.f;

    const unsigned smem_base = s2u(sm);

    // ldmatrix lane-dependent word offsets (within a buffer)
    const unsigned a_lane_off = (unsigned)((m0 + (lane & 15)) * P + ((lane >> 4) << 2));
    const unsigned b_lane_off = (unsigned)((nb + ((lane >> 4) & 1) * 8 + (lane & 7)) * P
                                           + ((lane >> 3) & 1) * 4);

    const int ar = tid >> 2;                  // A staging: row (0..63)
    const int aq = tid & 3;                   // A staging: 16B quarter of row

    // stage B chunk c into buffer c%4 via cp.async (1024 cp16 / 256 thr = 4)
    auto stageB = [&](int c) {
        const int kc = c * KC;
        const unsigned bb = smem_base + (STAGES * ASZ + (c & 3) * BSZ) * 4;
#pragma unroll
        for (int i = tid; i < NT * 4; i += NTHR) {
            int n = i >> 2, q = i & 3;
            cp16(bb + (n * P + q * 4) * 4, w1h + n * ENC_DIM + kc + q * 8);
        }
    };

    float4 fr[2];                              // A prefetch regs (8 floats)
    auto ldgA = [&](int c) {
        const float4* src = reinterpret_cast<const float4*>(
            enc + (row0 + ar) * ENC_DIM + c * KC + aq * 8);
        fr[0] = src[0]; fr[1] = src[1];
    };
    auto stsA = [&](int c) {
        __half2 h0 = __floats2half2_rn(fr[0].x, fr[0].y);
        __half2 h1 = __floats2half2_rn(fr[0].z, fr[0].w);
        __half2 h2 = __floats2half2_rn(fr[1].x, fr[1].y);
        __half2 h3 = __floats2half2_rn(fr[1].z, fr[1].w);
        uint4 w = make_uint4(*reinterpret_cast<uint32_t*>(&h0),
                             *reinterpret_cast<uint32_t*>(&h1),
                             *reinterpret_cast<uint32_t*>(&h2),
                             *reinterpret_cast<uint32_t*>(&h3));
        *reinterpret_cast<uint4*>(sm + (c & 3) * ASZ + ar * P + aq * 4) = w;
    };

    float d[2][8][4];
#pragma unroll
    for (int h = 0; h < 2; ++h)
#pragma unroll
        for (int j = 0; j < 8; ++j)
#pragma unroll
            for (int q = 0; q < 4; ++q) d[h][j][q] = 0.f;

    // prologue: B0..B2 in flight; A0..A2 staged; regs hold A3
    stageB(0); cp_commit();
    stageB(1); cp_commit();
    stageB(2); cp_commit();
    ldgA(0); stsA(0);
    ldgA(1); stsA(1);
    ldgA(2); stsA(2);
    ldgA(3);

    for (int c = 0; c < NCHUNK; ++c) {
        // group c must be complete; keep up to 2 younger groups in flight
        if (c <= NCHUNK - 3)      cp_wait<2>();
        else if (c == NCHUNK - 2) cp_wait<1>();
        else                      cp_wait<0>();
        __syncthreads();          // B(c) visible to all; buf (c+3)%4 free

        if (c + 3 < NCHUNK) {
            stsA(c + 3);          // from regs loaded last iter
            stageB(c + 3); cp_commit();
            ldgA(c + 4 < NCHUNK ? c + 4 : c + 3);   // prefetch next A
        }

        const int pb = c & 3;
        const unsigned abase = smem_base + (pb * ASZ) * 4 + a_lane_off * 4;
        const unsigned bbase = smem_base + (STAGES * ASZ + pb * BSZ) * 4
                               + b_lane_off * 4;

#pragma unroll
        for (int s = 0; s < NKS; ++s) {        // two k16 steps per chunk
            unsigned a[2][4];
            ldsm4(a[0], abase + (s * 8) * 4);
            ldsm4(a[1], abase + (16 * P + s * 8) * 4);
#pragma unroll
            for (int jp = 0; jp < 4; ++jp) {   // j-pairs
                unsigned bb[4];
                ldsm4(bb, bbase + (jp * 16 * P + s * 8) * 4);
                mma_f16(d[0][2 * jp],     a[0], bb[0], bb[1]);
                mma_f16(d[1][2 * jp],     a[1], bb[0], bb[1]);
                mma_f16(d[0][2 * jp + 1], a[0], bb[2], bb[3]);
                mma_f16(d[1][2 * jp + 1], a[1], bb[2], bb[3]);
            }
        }
    }

    // Epilogue: +dec_proj, tanh.approx, *v, warp-reduce n, 4-way smem combine
    const int g = lane >> 2;
#pragma unroll
    for (int h = 0; h < 2; ++h) {
        float s0 = 0.f, s1 = 0.f;
#pragma unroll
        for (int j = 0; j < 8; ++j) {
            const int n0 = nb + 8 * j + 2 * t;
            const float vv0 = vs[n0],  vv1 = vs[n0 + 1];
            const float dd0 = dps[n0], dd1 = dps[n0 + 1];
            s0 += vv0 * tanha(d[h][j][0] + dd0) + vv1 * tanha(d[h][j][1] + dd1);
            s1 += vv0 * tanha(d[h][j][2] + dd0) + vv1 * tanha(d[h][j][3] + dd1);
        }
        s0 += __shfl_xor_sync(0xffffffffu, s0, 1);
        s0 += __shfl_xor_sync(0xffffffffu, s0, 2);
        s1 += __shfl_xor_sync(0xffffffffu, s1, 1);
        s1 += __shfl_xor_sync(0xffffffffu, s1, 2);
        if (t == 0) {
            atomicAdd(&ssc[m0 + 16 * h + g], s0);
            atomicAdd(&ssc[m0 + 16 * h + 8 + g], s1);
        }
    }
    __syncthreads();
    if (tid < MT) scores[row0 + tid] = ssc[tid];
}

// ---------------------------------------------------------------------------
// K2: per-batch softmax over T -> probs (out[B*256 ..])
// ---------------------------------------------------------------------------
__global__ void softmax_kernel(const float* __restrict__ scores,
                               float* __restrict__ out,
                               int B, int T) {
    extern __shared__ float ss[];
    __shared__ float red[8];
    const int b = blockIdx.x;
    const int tid = threadIdx.x;
    const int lane = tid & 31, wid = tid >> 5;

    for (int t = tid; t < T; t += 256) ss[t] = scores[b * T + t];
    __syncthreads();

    float m = -CUDART_INF_F;
    for (int t = tid; t < T; t += 256) m = fmaxf(m, ss[t]);
#pragma unroll
    for (int o = 16; o; o >>= 1) m = fmaxf(m, __shfl_xor_sync(0xffffffffu, m, o));
    if (lane == 0) red[wid] = m;
    __syncthreads();
    if (tid == 0) {
        float mm = red[0];
#pragma unroll
        for (int w = 1; w < 8; ++w) mm = fmaxf(mm, red[w]);
        red[0] = mm;
    }
    __syncthreads();
    m = red[0];
    __syncthreads();

    float z = 0.f;
    for (int t = tid; t < T; t += 256) z += expf(ss[t] - m);
#pragma unroll
    for (int o = 16; o; o >>= 1) z += __shfl_xor_sync(0xffffffffu, z, o);
    if (lane == 0) red[wid] = z;
    __syncthreads();
    if (tid == 0) {
        float zz = 0.f;
#pragma unroll
        for (int w = 0; w < 8; ++w) zz += red[w];
        red[0] = zz;
    }
    __syncthreads();
    const float inv = 1.f / red[0];

    float* probs = out + (long long)B * ENC_DIM;
    for (int t = tid; t < T; t += 256)
        probs[(long long)b * T + t] = expf(ss[t] - m) * inv;
}

// ---------------------------------------------------------------------------
// K3: context partials. grid (B, NC). 4 accumulators for MLP.
// ---------------------------------------------------------------------------
__global__ void ctx_partial_kernel(const float* __restrict__ enc,
                                   const float* __restrict__ out_probs,
                                   float* __restrict__ part,
                                   int B, int T) {
    __shared__ float ps[2048 / NC];
    const int b = blockIdx.x;
    const int c = blockIdx.y;
    const int tid = threadIdx.x;
    const int TC = T / NC;                       // 64
    const long long t0 = (long long)c * TC;

    if (tid < TC) ps[tid] = out_probs[(long long)b * T + t0 + tid];
    __syncthreads();

    float a0 = 0.f, a1 = 0.f, a2 = 0.f, a3 = 0.f;
    const float* e = enc + ((long long)b * T + t0) * ENC_DIM + tid;
#pragma unroll 4
    for (int t = 0; t < TC; t += 4) {
        a0 = fmaf(ps[t],     __ldg(e + (long long)t * ENC_DIM),       a0);
        a1 = fmaf(ps[t + 1], __ldg(e + (long long)(t + 1) * ENC_DIM), a1);
        a2 = fmaf(ps[t + 2], __ldg(e + (long long)(t + 2) * ENC_DIM), a2);
        a3 = fmaf(ps[t + 3], __ldg(e + (long long)(t + 3) * ENC_DIM), a3);
    }
    part[((long long)c * B + b) * ENC_DIM + tid] = (a0 + a1) + (a2 + a3);
}

// ---------------------------------------------------------------------------
// K4: reduce partials -> out context region
// ---------------------------------------------------------------------------
__global__ void ctx_reduce_kernel(const float* __restrict__ part,
                                  float* __restrict__ out, int B) {
    const int b = blockIdx.x;
    const int tid = threadIdx.x;
    float acc = 0.f;
#pragma unroll
    for (int c = 0; c < NC; ++c)
        acc += part[((long long)c * B + b) * ENC_DIM + tid];
    out[b * ENC_DIM + tid] = acc;
}

// ---------------------------------------------------------------------------
extern "C" void kernel_launch(void* const* d_in, const int* in_sizes, int n_in,
                              void* d_out, int out_size) {
    const float* enc = (const float*)d_in[0];   // [B,T,256]
    const float* dec = (const float*)d_in[1];   // [B,256]
    const float* w1  = (const float*)d_in[2];   // [256,256]
    const float* w2  = (const float*)d_in[3];   // [256,256]
    const float* v   = (const float*)d_in[4];   // [1,256]
    float* out = (float*)d_out;

    const int B = in_sizes[1] / ENC_DIM;                 // 64
    const int T = in_sizes[0] / (B * ENC_DIM);           // 2048

    float*  dp_ptr;     cudaGetSymbolAddress((void**)&dp_ptr, g_dp);
    float*  scores_ptr; cudaGetSymbolAddress((void**)&scores_ptr, g_scores);
    __half* w1h_ptr;    cudaGetSymbolAddress((void**)&w1h_ptr, g_w1h);
    float*  part_ptr;   cudaGetSymbolAddress((void**)&part_ptr, g_part);

    cudaFuncSetAttribute(scores_mma_kernel,
                         cudaFuncAttributeMaxDynamicSharedMemorySize, DYN_BYTES);

    prep_kernel<<<B, 256>>>(dec, w2, w1, w1h_ptr, dp_ptr);
    scores_mma_kernel<<<(B * T) / MT, NTHR, DYN_BYTES>>>(enc, w1h_ptr, dp_ptr, v,
                                                         scores_ptr, T);
    softmax_kernel<<<B, 256, T * (int)sizeof(float)>>>(scores_ptr, out, B, T);
    ctx_partial_kernel<<<dim3(B, NC), 256>>>(enc, out + (long long)B * ENC_DIM,
                                             part_ptr, B, T);
    ctx_reduce_kernel<<<B, 256>>>(part_ptr, out, B);
}

// round 12
// speedup vs baseline: 1.1365x; 1.1365x over previous
#include <cuda_runtime.h>
#include <cuda_fp16.h>
#include <cuda_bf16.h>
#include <math_constants.h>
#include <cstdint>

#define ENC_DIM 256
#define INT_DIM 256
#define MT 64                   // rows per CTA (M)
#define NT 256                  // hidden per CTA (N)
#define KC 32                   // k per chunk
#define NCHUNK (ENC_DIM / KC)   // 8
#define NKS (KC / 16)           // 2 k16 steps per chunk
#define P 20                    // smem pitch in u32 words (16 used + 4 pad)
#define ASZ (MT * P)            // 1280 words (one A chunk buffer)
#define BSZ (NT * P)            // 5120 words (one B stage)
#define BSTG 3                  // B pipeline stages
#define DYN_BYTES ((NCHUNK * ASZ + BSTG * BSZ) * 4)   // 102400 -> 2 CTAs/SM
#define NTHR 256
#define MAXCPB 32               // chunks per batch (T/MT)

// Scratch (allocation-free rule: __device__ globals)
__device__ float  g_dp[64 * INT_DIM];          // dec_proj [B, I]
__device__ float  g_scores[64 * 2048];         // scores   [B, T]
__device__ __half g_w1h[INT_DIM * ENC_DIM];    // w1 as fp16, [n][k]
__device__ float  g_pm[2048];                  // per-CTA local max
__device__ float  g_pz[2048];                  // per-CTA local exp-sum
__device__ float  g_pctx[2048 * ENC_DIM];      // per-CTA partial context
__device__ float  g_mz[128];                   // per-batch {m, Z}

// ---------------------------------------------------------------------------
// helpers
// ---------------------------------------------------------------------------
__device__ __forceinline__ float tanha(float x) {
    float y;
    asm("tanh.approx.f32 %0, %1;" : "=f"(y) : "f"(x));
    return y;
}
__device__ __forceinline__ void cp16(unsigned dst_s, const void* src) {
    asm volatile("cp.async.cg.shared.global [%0], [%1], 16;"
                 :: "r"(dst_s), "l"(src) : "memory");
}
__device__ __forceinline__ void cp_commit() {
    asm volatile("cp.async.commit_group;" ::: "memory");
}
template <int N>
__device__ __forceinline__ void cp_wait() {
    asm volatile("cp.async.wait_group %0;" :: "n"(N) : "memory");
}
__device__ __forceinline__ unsigned s2u(const void* p) {
    return (unsigned)__cvta_generic_to_shared(p);
}
__device__ __forceinline__ void ldsm4(unsigned r[4], unsigned addr) {
    asm volatile("ldmatrix.sync.aligned.m8n8.x4.shared.b16 "
                 "{%0,%1,%2,%3}, [%4];"
                 : "=r"(r[0]), "=r"(r[1]), "=r"(r[2]), "=r"(r[3])
                 : "r"(addr));
}
__device__ __forceinline__ void mma_f16(float d[4], const unsigned a[4],
                                        unsigned b0, unsigned b1) {
    asm volatile(
        "mma.sync.aligned.m16n8k16.row.col.f32.f16.f16.f32 "
        "{%0,%1,%2,%3}, {%4,%5,%6,%7}, {%8,%9}, {%0,%1,%2,%3};"
        : "+f"(d[0]), "+f"(d[1]), "+f"(d[2]), "+f"(d[3])
        : "r"(a[0]), "r"(a[1]), "r"(a[2]), "r"(a[3]), "r"(b0), "r"(b1));
}

// ---------------------------------------------------------------------------
// K0: fused prep (dec_proj + w1 -> fp16). grid = 64 x 256.
// ---------------------------------------------------------------------------
__global__ void prep_kernel(const float* __restrict__ dec,
                            const float* __restrict__ w2,
                            const float* __restrict__ w1,
                            __half* __restrict__ w1h,
                            float* __restrict__ dp) {
    __shared__ float ds[ENC_DIM];
    const int b = blockIdx.x;
    const int tid = threadIdx.x;
    const int lane = tid & 31, wid = tid >> 5;

    ds[tid] = dec[b * ENC_DIM + tid];

    {
        const int base = b * 1024 + tid * 4;
        float4 wv = *reinterpret_cast<const float4*>(w1 + base);
        __half2 p0 = __floats2half2_rn(wv.x, wv.y);
        __half2 p1 = __floats2half2_rn(wv.z, wv.w);
        uint2 pk = make_uint2(*reinterpret_cast<uint32_t*>(&p0),
                              *reinterpret_cast<uint32_t*>(&p1));
        *reinterpret_cast<uint2*>(w1h + base) = pk;
    }
    __syncthreads();

#pragma unroll 4
    for (int ii = 0; ii < 32; ++ii) {
        const int i = wid * 32 + ii;
        float acc = 0.f;
#pragma unroll
        for (int kk = 0; kk < 8; ++kk) {
            const int k = kk * 32 + lane;
            acc = fmaf(__ldg(w2 + i * ENC_DIM + k), ds[k], acc);
        }
#pragma unroll
        for (int o = 16; o; o >>= 1) acc += __shfl_xor_sync(0xffffffffu, acc, o);
        if (lane == 0) dp[b * INT_DIM + i] = acc;
    }
}

// ---------------------------------------------------------------------------
// K1: scores + fused partial-softmax/partial-context.
// CTA = 64 rows x 256 n, 256 thr, 2 CTAs/SM. A resident (8 chunk buffers),
// B 3-stage cp.async pipeline. After GEMM epilogue, CTA computes
// m_c, Z_c, ctx_c from its own fp16 A tile in smem (flash-style partials).
// ---------------------------------------------------------------------------
__global__ void __launch_bounds__(NTHR, 2)
scores_mma_kernel(const float* __restrict__ enc,
                  const __half* __restrict__ w1h,
                  const float* __restrict__ dp,
                  const float* __restrict__ v,
                  float* __restrict__ scores,
                  float* __restrict__ pm,
                  float* __restrict__ pz,
                  float* __restrict__ pctx,
                  int T) {
    extern __shared__ unsigned sm[];          // A0..A7 | B0..B2
    __shared__ float dps[INT_DIM], vs[INT_DIM], ssc[MT];
    __shared__ float redm[2], redz[2], mc_sh;

    const int tid  = threadIdx.x;
    const int wid  = tid >> 5;
    const int lane = tid & 31;
    const int t    = lane & 3;
    const int m0   = (wid & 1) * 32;
    const int nb   = (wid >> 1) * 64;
    const int bid  = blockIdx.x;
    const long long row0 = (long long)bid * MT;
    const int b = (int)(row0 / T);

    dps[tid] = dp[b * INT_DIM + tid];
    vs[tid]  = __ldg(v + tid);
    if (tid < MT) ssc[tid] = 0.f;

    const unsigned smem_base = s2u(sm);

    const unsigned a_lane_off = (unsigned)((m0 + (lane & 15)) * P + ((lane >> 4) << 2));
    const unsigned b_lane_off = (unsigned)((nb + ((lane >> 4) & 1) * 8 + (lane & 7)) * P
                                           + ((lane >> 3) & 1) * 4);

    const int ar = tid >> 2;                  // A staging: row (0..63)
    const int aq = tid & 3;                   // A staging: 16B quarter of row

    // stage B chunk c into buffer c%3 via cp.async
    auto stageB = [&](int c) {
        const int kc = c * KC;
        const unsigned bb = smem_base + (NCHUNK * ASZ + (c % 3) * BSZ) * 4;
#pragma unroll
        for (int i = tid; i < NT * 4; i += NTHR) {
            int n = i >> 2, q = i & 3;
            cp16(bb + (n * P + q * 4) * 4, w1h + n * ENC_DIM + kc + q * 8);
        }
    };

    float4 fr[2];                              // A prefetch regs (8 floats)
    auto ldgA = [&](int c) {
        const float4* src = reinterpret_cast<const float4*>(
            enc + (row0 + ar) * ENC_DIM + c * KC + aq * 8);
        fr[0] = src[0]; fr[1] = src[1];
    };
    auto stsA = [&](int c) {                   // A buffer c is unique: no reuse
        __half2 h0 = __floats2half2_rn(fr[0].x, fr[0].y);
        __half2 h1 = __floats2half2_rn(fr[0].z, fr[0].w);
        __half2 h2 = __floats2half2_rn(fr[1].x, fr[1].y);
        __half2 h3 = __floats2half2_rn(fr[1].z, fr[1].w);
        uint4 w = make_uint4(*reinterpret_cast<uint32_t*>(&h0),
                             *reinterpret_cast<uint32_t*>(&h1),
                             *reinterpret_cast<uint32_t*>(&h2),
                             *reinterpret_cast<uint32_t*>(&h3));
        *reinterpret_cast<uint4*>(sm + c * ASZ + ar * P + aq * 4) = w;
    };

    float d[2][8][4];
#pragma unroll
    for (int h = 0; h < 2; ++h)
#pragma unroll
        for (int j = 0; j < 8; ++j)
#pragma unroll
            for (int q = 0; q < 4; ++q) d[h][j][q] = 0.f;

    // prologue: B0,B1 in flight; A0,A1 staged; regs hold A2
    stageB(0); cp_commit();
    stageB(1); cp_commit();
    ldgA(0); stsA(0);
    ldgA(1); stsA(1);
    ldgA(2);

    for (int c = 0; c < NCHUNK; ++c) {
        if (c < NCHUNK - 1) cp_wait<1>(); else cp_wait<0>();
        __syncthreads();          // B(c) + A(c) visible; B buf (c+2)%3 free

        if (c + 2 < NCHUNK) {
            stsA(c + 2);          // from regs loaded last iter
            stageB(c + 2); cp_commit();
            if (c + 3 < NCHUNK) ldgA(c + 3);
        }

        const unsigned abase = smem_base + (c * ASZ) * 4 + a_lane_off * 4;
        const unsigned bbase = smem_base + (NCHUNK * ASZ + (c % 3) * BSZ) * 4
                               + b_lane_off * 4;

#pragma unroll
        for (int s = 0; s < NKS; ++s) {
            unsigned a[2][4];
            ldsm4(a[0], abase + (s * 8) * 4);
            ldsm4(a[1], abase + (16 * P + s * 8) * 4);
#pragma unroll
            for (int jp = 0; jp < 4; ++jp) {
                unsigned bb[4];
                ldsm4(bb, bbase + (jp * 16 * P + s * 8) * 4);
                mma_f16(d[0][2 * jp],     a[0], bb[0], bb[1]);
                mma_f16(d[1][2 * jp],     a[1], bb[0], bb[1]);
                mma_f16(d[0][2 * jp + 1], a[0], bb[2], bb[3]);
                mma_f16(d[1][2 * jp + 1], a[1], bb[2], bb[3]);
            }
        }
    }

    // Score epilogue: +dec_proj, tanh.approx, *v, warp-reduce, smem combine
    const int g = lane >> 2;
#pragma unroll
    for (int h = 0; h < 2; ++h) {
        float s0 = 0.f, s1 = 0.f;
#pragma unroll
        for (int j = 0; j < 8; ++j) {
            const int n0 = nb + 8 * j + 2 * t;
            const float vv0 = vs[n0],  vv1 = vs[n0 + 1];
            const float dd0 = dps[n0], dd1 = dps[n0 + 1];
            s0 += vv0 * tanha(d[h][j][0] + dd0) + vv1 * tanha(d[h][j][1] + dd1);
            s1 += vv0 * tanha(d[h][j][2] + dd0) + vv1 * tanha(d[h][j][3] + dd1);
        }
        s0 += __shfl_xor_sync(0xffffffffu, s0, 1);
        s0 += __shfl_xor_sync(0xffffffffu, s0, 2);
        s1 += __shfl_xor_sync(0xffffffffu, s1, 1);
        s1 += __shfl_xor_sync(0xffffffffu, s1, 2);
        if (t == 0) {
            atomicAdd(&ssc[m0 + 16 * h + g], s0);
            atomicAdd(&ssc[m0 + 16 * h + 8 + g], s1);
        }
    }
    __syncthreads();
    if (tid < MT) scores[row0 + tid] = ssc[tid];

    // ---- fused partial softmax + partial context (flash-style) ----
    // local max over the 64 scores (2 warps)
    if (tid < MT) {
        float s = ssc[tid];
#pragma unroll
        for (int o = 16; o; o >>= 1) s = fmaxf(s, __shfl_xor_sync(0xffffffffu, s, o));
        if (lane == 0) redm[wid] = s;
    }
    __syncthreads();
    if (tid == 0) mc_sh = fmaxf(redm[0], redm[1]);
    __syncthreads();
    const float m_c = mc_sh;

    // p~ = exp(s - m_c), Z_c
    if (tid < MT) {
        float p = expf(ssc[tid] - m_c);
        ssc[tid] = p;                          // overwrite with weights
        float z = p;
#pragma unroll
        for (int o = 16; o; o >>= 1) z += __shfl_xor_sync(0xffffffffu, z, o);
        if (lane == 0) redz[wid] = z;
    }
    __syncthreads();
    if (tid == 0) {
        pm[bid] = m_c;
        pz[bid] = redz[0] + redz[1];
    }

    // partial context: thread owns column e = tid; reads resident fp16 A
    {
        const int ch   = tid >> 5;             // chunk buffer holding k = e
        const int woff = (tid & 31) >> 1;      // word within row
        const int hh   = tid & 1;
        const unsigned* abuf = sm + ch * ASZ + woff;
        float acc = 0.f;
#pragma unroll 8
        for (int r = 0; r < MT; ++r) {
            unsigned w = abuf[r * P];
            __half2 hx = *reinterpret_cast<__half2*>(&w);
            float x = hh ? __high2float(hx) : __low2float(hx);
            acc = fmaf(ssc[r], x, acc);
        }
        pctx[(long long)bid * ENC_DIM + tid] = acc;
    }
}

// ---------------------------------------------------------------------------
// K2: combine partials per batch (exact flash rescale) -> context + {m, Z}
// ---------------------------------------------------------------------------
__global__ void combine_kernel(const float* __restrict__ pm,
                               const float* __restrict__ pz,
                               const float* __restrict__ pctx,
                               float* __restrict__ out,
                               float* __restrict__ mz,
                               int cpb) {
    __shared__ float mc[MAXCPB], wc[MAXCPB];
    __shared__ float m_sh, z_sh;
    const int b = blockIdx.x;
    const int tid = threadIdx.x;

    if (tid < cpb) mc[tid] = pm[b * cpb + tid];
    __syncthreads();
    if (tid == 0) {
        float m = mc[0];
        for (int c = 1; c < cpb; ++c) m = fmaxf(m, mc[c]);
        m_sh = m;
    }
    __syncthreads();
    const float m = m_sh;
    if (tid < cpb) wc[tid] = expf(mc[tid] - m);
    __syncthreads();
    if (tid == 0) {
        float z = 0.f;
        for (int c = 0; c < cpb; ++c) z += pz[b * cpb + c] * wc[c];
        z_sh = z;
        mz[2 * b] = m;
        mz[2 * b + 1] = z;
    }
    __syncthreads();
    const float invZ = 1.f / z_sh;

    float acc = 0.f;
    for (int c = 0; c < cpb; ++c)
        acc = fmaf(pctx[((long long)(b * cpb + c)) * ENC_DIM + tid], wc[c], acc);
    out[b * ENC_DIM + tid] = acc * invZ;
}

// ---------------------------------------------------------------------------
// K3: probs = exp(score - m) / Z
// ---------------------------------------------------------------------------
__global__ void probs_kernel(const float* __restrict__ scores,
                             const float* __restrict__ mz,
                             float* __restrict__ out,
                             int B, int T) {
    const int b = blockIdx.x;
    const int tid = threadIdx.x;
    const float m = mz[2 * b];
    const float inv = 1.f / mz[2 * b + 1];
    float* probs = out + (long long)B * ENC_DIM;
    for (int t = tid; t < T; t += 256)
        probs[(long long)b * T + t] = expf(scores[b * T + t] - m) * inv;
}

// ---------------------------------------------------------------------------
extern "C" void kernel_launch(void* const* d_in, const int* in_sizes, int n_in,
                              void* d_out, int out_size) {
    const float* enc = (const float*)d_in[0];   // [B,T,256]
    const float* dec = (const float*)d_in[1];   // [B,256]
    const float* w1  = (const float*)d_in[2];   // [256,256]
    const float* w2  = (const float*)d_in[3];   // [256,256]
    const float* v   = (const float*)d_in[4];   // [1,256]
    float* out = (float*)d_out;

    const int B = in_sizes[1] / ENC_DIM;                 // 64
    const int T = in_sizes[0] / (B * ENC_DIM);           // 2048
    const int cpb = T / MT;                              // 32

    float*  dp_ptr;     cudaGetSymbolAddress((void**)&dp_ptr, g_dp);
    float*  scores_ptr; cudaGetSymbolAddress((void**)&scores_ptr, g_scores);
    __half* w1h_ptr;    cudaGetSymbolAddress((void**)&w1h_ptr, g_w1h);
    float*  pm_ptr;     cudaGetSymbolAddress((void**)&pm_ptr, g_pm);
    float*  pz_ptr;     cudaGetSymbolAddress((void**)&pz_ptr, g_pz);
    float*  pctx_ptr;   cudaGetSymbolAddress((void**)&pctx_ptr, g_pctx);
    float*  mz_ptr;     cudaGetSymbolAddress((void**)&mz_ptr, g_mz);

    cudaFuncSetAttribute(scores_mma_kernel,
                         cudaFuncAttributeMaxDynamicSharedMemorySize, DYN_BYTES);

    prep_kernel<<<B, 256>>>(dec, w2, w1, w1h_ptr, dp_ptr);
    scores_mma_kernel<<<(B * T) / MT, NTHR, DYN_BYTES>>>(
        enc, w1h_ptr, dp_ptr, v, scores_ptr, pm_ptr, pz_ptr, pctx_ptr, T);
    combine_kernel<<<B, 256>>>(pm_ptr, pz_ptr, pctx_ptr, out, mz_ptr, cpb);
    probs_kernel<<<B, 256>>>(scores_ptr, mz_ptr, out, B, T);
}